// round 2
// baseline (speedup 1.0000x reference)
#include <cuda_runtime.h>

#define B  64
#define L  512
#define HB 768
#define HC 1024
#define H  (HB + HC)   // 1792
#define NL 7

// Scratch (no allocations allowed): compaction index + per-row valid count.
__device__ int g_idx[B * L];
__device__ int g_count[B];

// ---------------------------------------------------------------------------
// Kernel 1: per-batch-row stable compaction index via warp ballot scan.
// One warp per row; 16 iterations of 32 lanes over L=512.
// ---------------------------------------------------------------------------
__global__ void build_idx_kernel(const int* __restrict__ valid) {
    int b    = blockIdx.x;
    int lane = threadIdx.x;
    int base = b * L;
    int count = 0;
#pragma unroll
    for (int i = 0; i < L; i += 32) {
        int v = valid[base + i + lane];
        unsigned m = __ballot_sync(0xffffffffu, v != 0);
        if (v) {
            int pos = count + __popc(m & ((1u << lane) - 1u));
            g_idx[base + pos] = i + lane;
        }
        count += __popc(m);
    }
    if (lane == 0) g_count[b] = count;
}

// ---------------------------------------------------------------------------
// Packed f32x2 FMA (Blackwell): two independent rn-FMAs per issue.
// ptxas never auto-fuses 2x fmaf from C++ — must come from PTX.
// ---------------------------------------------------------------------------
__device__ __forceinline__ void ffma2(unsigned long long& d,
                                      unsigned long long a,
                                      unsigned long long b) {
    asm("fma.rn.f32x2 %0, %1, %2, %0;" : "+l"(d) : "l"(a), "l"(b));
}

__device__ __forceinline__ float pairsum(unsigned long long d) {
    float lo, hi;
    asm("mov.b64 {%0, %1}, %2;" : "=f"(lo), "=f"(hi) : "l"(d));
    return lo + hi;
}

// ---------------------------------------------------------------------------
// Kernel 2: fused gather + concat + [BL,1792]x[1792,7] matmul + bias.
// Warp processes TG=4 consecutive tokens (same batch row since L%4==0).
// Lane owns a 4-float h-slice per 128-float chunk; weights staged transposed
// in dynamic SMEM ([NL][H]) and reused across the 4 tokens in registers.
// ---------------------------------------------------------------------------
#define TPB 256
#define WPB (TPB / 32)
#define TG  4

__global__ __launch_bounds__(TPB, 2) void tag_kernel(
    const float* __restrict__ bert,
    const float* __restrict__ comet,
    const float* __restrict__ w,      // [H, NL] row-major
    const float* __restrict__ bias,   // [NL]
    float* __restrict__ out,          // [B, L, NL]
    int total_warps)
{
    extern __shared__ float sW[];     // [NL][H] transposed, 50176 B

    for (int i = threadIdx.x; i < H * NL; i += TPB) {
        int h = i / NL;
        int n = i - h * NL;
        sW[n * H + h] = w[i];
    }
    __syncthreads();

    int lane  = threadIdx.x & 31;
    int warp  = threadIdx.x >> 5;
    int gwarp = blockIdx.x * WPB + warp;
    float bias_r = (lane < NL) ? bias[lane] : 0.0f;
    int hb = lane * 4;

    const ulonglong2 zero2 = make_ulonglong2(0ull, 0ull);

    const int ngroups = (B * L) / TG;  // 8192
    for (int g = gwarp; g < ngroups; g += total_warps) {
        int tok0 = g * TG;
        int b    = tok0 >> 9;          // / L
        int p0   = tok0 & (L - 1);
        int cnt  = g_count[b];

        const float* brow[TG];
        bool hasb[TG];
#pragma unroll
        for (int t = 0; t < TG; t++) {
            bool v  = (p0 + t) < cnt;
            hasb[t] = v;
            int j   = v ? g_idx[b * L + p0 + t] : 0;
            brow[t] = bert + (size_t)(b * L + j) * HB;
        }

        unsigned long long acc[TG][NL];
#pragma unroll
        for (int t = 0; t < TG; t++)
#pragma unroll
            for (int n = 0; n < NL; n++) acc[t][n] = 0ull;

        // --- bert segment: 6 chunks of 128 floats ---
#pragma unroll
        for (int c = 0; c < HB / 128; c++) {
            int h = c * 128 + hb;
            ulonglong2 wv[NL];
#pragma unroll
            for (int n = 0; n < NL; n++)
                wv[n] = *reinterpret_cast<const ulonglong2*>(&sW[n * H + h]);
#pragma unroll
            for (int t = 0; t < TG; t++) {
                ulonglong2 x = hasb[t]
                    ? *reinterpret_cast<const ulonglong2*>(brow[t] + h)
                    : zero2;
#pragma unroll
                for (int n = 0; n < NL; n++) {
                    ffma2(acc[t][n], x.x, wv[n].x);
                    ffma2(acc[t][n], x.y, wv[n].y);
                }
            }
        }

        // --- comet segment: 8 chunks of 128 floats ---
        const float* crow0 = comet + (size_t)(b * L + p0) * HC;
#pragma unroll
        for (int c = 0; c < HC / 128; c++) {
            int h  = HB + c * 128 + hb;   // weight index
            int hc = c * 128 + hb;        // comet index
            ulonglong2 wv[NL];
#pragma unroll
            for (int n = 0; n < NL; n++)
                wv[n] = *reinterpret_cast<const ulonglong2*>(&sW[n * H + h]);
#pragma unroll
            for (int t = 0; t < TG; t++) {
                ulonglong2 x =
                    *reinterpret_cast<const ulonglong2*>(crow0 + t * HC + hc);
#pragma unroll
                for (int n = 0; n < NL; n++) {
                    ffma2(acc[t][n], x.x, wv[n].x);
                    ffma2(acc[t][n], x.y, wv[n].y);
                }
            }
        }

        // --- butterfly reduce across lanes; lanes 0..6 write logits ---
#pragma unroll
        for (int t = 0; t < TG; t++) {
            float v = 0.0f;
#pragma unroll
            for (int n = 0; n < NL; n++) {
                float s = pairsum(acc[t][n]);
                s += __shfl_xor_sync(0xffffffffu, s, 16);
                s += __shfl_xor_sync(0xffffffffu, s, 8);
                s += __shfl_xor_sync(0xffffffffu, s, 4);
                s += __shfl_xor_sync(0xffffffffu, s, 2);
                s += __shfl_xor_sync(0xffffffffu, s, 1);
                if (lane == n) v = s;   // constant-index select, no spill
            }
            if (lane < NL)
                out[(size_t)(tok0 + t) * NL + lane] = v + bias_r;
        }
    }
}

// ---------------------------------------------------------------------------
extern "C" void kernel_launch(void* const* d_in, const int* in_sizes, int n_in,
                              void* d_out, int out_size) {
    const float* bert  = (const float*)d_in[0];
    const float* comet = (const float*)d_in[1];
    const int*   valid = (const int*)d_in[2];
    const float* w     = (const float*)d_in[3];
    const float* bias  = (const float*)d_in[4];
    float*       out   = (float*)d_out;

    build_idx_kernel<<<B, 32>>>(valid);

    const int smem = H * NL * (int)sizeof(float);  // 50176 B > 48K default
    cudaFuncSetAttribute(tag_kernel,
                         cudaFuncAttributeMaxDynamicSharedMemorySize, smem);

    const int grid = 296;  // 2 blocks/SM on 148 SMs, single wave
    tag_kernel<<<grid, TPB, smem>>>(bert, comet, w, bias, out, grid * WPB);
}

// round 3
// speedup vs baseline: 1.0329x; 1.0329x over previous
#include <cuda_runtime.h>

#define B  64
#define L  512
#define HB 768
#define HC 1024
#define H  (HB + HC)   // 1792
#define NL 7
#define NCH (H / 128)  // 14 chunks of 128 floats
#define BCH (HB / 128) // 6 bert chunks

// Scratch (no allocations allowed): compaction index + per-row valid count.
__device__ int g_idx[B * L];
__device__ int g_count[B];

// ---------------------------------------------------------------------------
// Kernel 1: per-batch-row stable compaction via warp ballot scan.
// All 16 row-loads issued upfront (MLP=16) so the scan isn't latency-serial.
// ---------------------------------------------------------------------------
__global__ void build_idx_kernel(const int* __restrict__ valid) {
    int b    = blockIdx.x;
    int lane = threadIdx.x;
    int base = b * L;

    int v[L / 32];
#pragma unroll
    for (int k = 0; k < L / 32; k++)
        v[k] = valid[base + k * 32 + lane];

    int count = 0;
#pragma unroll
    for (int k = 0; k < L / 32; k++) {
        unsigned m = __ballot_sync(0xffffffffu, v[k] != 0);
        if (v[k]) {
            int pos = count + __popc(m & ((1u << lane) - 1u));
            g_idx[base + pos] = k * 32 + lane;
        }
        count += __popc(m);
    }
    if (lane == 0) g_count[b] = count;
}

// ---------------------------------------------------------------------------
// Packed f32x2 FMA (Blackwell): two independent rn-FMAs per issue.
// ---------------------------------------------------------------------------
__device__ __forceinline__ void ffma2(unsigned long long& d,
                                      unsigned long long a,
                                      unsigned long long b) {
    asm("fma.rn.f32x2 %0, %1, %2, %0;" : "+l"(d) : "l"(a), "l"(b));
}

__device__ __forceinline__ float pairsum(unsigned long long d) {
    float lo, hi;
    asm("mov.b64 {%0, %1}, %2;" : "=f"(lo), "=f"(hi) : "l"(d));
    return lo + hi;
}

// ---------------------------------------------------------------------------
// Kernel 2: fused gather + concat + [BL,1792]x[1792,7] matmul + bias.
// Warp = TG=4 consecutive tokens. Lane owns 4 floats per 128-float chunk.
// Unified 14-chunk loop with double-buffered global loads (prefetch c+1
// during compute of c) to keep 4 loads per warp continuously in flight.
// ---------------------------------------------------------------------------
#define TPB 256
#define WPB (TPB / 32)
#define TG  4

__global__ __launch_bounds__(TPB, 2) void tag_kernel(
    const float* __restrict__ bert,
    const float* __restrict__ comet,
    const float* __restrict__ w,      // [H, NL] row-major
    const float* __restrict__ bias,   // [NL]
    float* __restrict__ out,          // [B, L, NL]
    int total_warps)
{
    extern __shared__ float sW[];     // [NL][H] transposed, 50176 B

    for (int i = threadIdx.x; i < H * NL; i += TPB) {
        int h = i / NL;
        int n = i - h * NL;
        sW[n * H + h] = w[i];
    }
    __syncthreads();

    int lane  = threadIdx.x & 31;
    int warp  = threadIdx.x >> 5;
    int gwarp = blockIdx.x * WPB + warp;
    float bias_r = (lane < NL) ? bias[lane] : 0.0f;
    int hb = lane * 4;

    const ulonglong2 zero2 = make_ulonglong2(0ull, 0ull);

    const int ngroups = (B * L) / TG;  // 8192
    for (int g = gwarp; g < ngroups; g += total_warps) {
        int tok0 = g * TG;
        int b    = tok0 >> 9;          // / L
        int p0   = tok0 & (L - 1);
        int cnt  = g_count[b];

        const float* brow[TG];
        bool hasb[TG];
#pragma unroll
        for (int t = 0; t < TG; t++) {
            bool v  = (p0 + t) < cnt;
            hasb[t] = v;
            int j   = v ? g_idx[b * L + p0 + t] : 0;
            brow[t] = bert + (size_t)(b * L + j) * HB;
        }
        const float* crow0 = comet + (size_t)(b * L + p0) * HC;

        unsigned long long acc[TG][NL];
#pragma unroll
        for (int t = 0; t < TG; t++)
#pragma unroll
            for (int n = 0; n < NL; n++) acc[t][n] = 0ull;

        // Double-buffered token data: xb[buf][token] = 16 B slice of chunk.
        ulonglong2 xb[2][TG];

        // Prime: load chunk 0 (bert) for all 4 tokens.
#pragma unroll
        for (int t = 0; t < TG; t++)
            xb[0][t] = hasb[t]
                ? *reinterpret_cast<const ulonglong2*>(brow[t] + hb)
                : zero2;

#pragma unroll
        for (int c = 0; c < NCH; c++) {
            // Prefetch chunk c+1 while computing chunk c.
            if (c + 1 < NCH) {
                int nc = c + 1;
#pragma unroll
                for (int t = 0; t < TG; t++) {
                    if (nc < BCH) {
                        xb[(c + 1) & 1][t] = hasb[t]
                            ? *reinterpret_cast<const ulonglong2*>(
                                  brow[t] + nc * 128 + hb)
                            : zero2;
                    } else {
                        xb[(c + 1) & 1][t] =
                            *reinterpret_cast<const ulonglong2*>(
                                crow0 + t * HC + (nc - BCH) * 128 + hb);
                    }
                }
            }

            // Compute chunk c: weight index is uniformly c*128+hb.
            int h = c * 128 + hb;
#pragma unroll
            for (int n = 0; n < NL; n++) {
                ulonglong2 wv =
                    *reinterpret_cast<const ulonglong2*>(&sW[n * H + h]);
#pragma unroll
                for (int t = 0; t < TG; t++) {
                    ffma2(acc[t][n], xb[c & 1][t].x, wv.x);
                    ffma2(acc[t][n], xb[c & 1][t].y, wv.y);
                }
            }
        }

        // --- butterfly reduce across lanes; lanes 0..6 write logits ---
#pragma unroll
        for (int t = 0; t < TG; t++) {
            float v = 0.0f;
#pragma unroll
            for (int n = 0; n < NL; n++) {
                float s = pairsum(acc[t][n]);
                s += __shfl_xor_sync(0xffffffffu, s, 16);
                s += __shfl_xor_sync(0xffffffffu, s, 8);
                s += __shfl_xor_sync(0xffffffffu, s, 4);
                s += __shfl_xor_sync(0xffffffffu, s, 2);
                s += __shfl_xor_sync(0xffffffffu, s, 1);
                if (lane == n) v = s;   // constant-index select, no spill
            }
            if (lane < NL)
                out[(size_t)(tok0 + t) * NL + lane] = v + bias_r;
        }
    }
}

// ---------------------------------------------------------------------------
extern "C" void kernel_launch(void* const* d_in, const int* in_sizes, int n_in,
                              void* d_out, int out_size) {
    const float* bert  = (const float*)d_in[0];
    const float* comet = (const float*)d_in[1];
    const int*   valid = (const int*)d_in[2];
    const float* w     = (const float*)d_in[3];
    const float* bias  = (const float*)d_in[4];
    float*       out   = (float*)d_out;

    build_idx_kernel<<<B, 32>>>(valid);

    const int smem = H * NL * (int)sizeof(float);  // 50176 B > 48K default
    cudaFuncSetAttribute(tag_kernel,
                         cudaFuncAttributeMaxDynamicSharedMemorySize, smem);

    const int grid = 296;  // 2 blocks/SM on 148 SMs, single wave
    tag_kernel<<<grid, TPB, smem>>>(bert, comet, w, bias, out, grid * WPB);
}